// round 13
// baseline (speedup 1.0000x reference)
#include <cuda_runtime.h>
#include <cuda_fp16.h>
#include <cstdint>

#define MDIM 16384
#define NDIM 2048
#define KDIM 2048

#define BM 256
#define BN 256
#define BK 32
#define LDSX 40                         // padded smem row stride (elements)
#define TILE_BYTES (BM * LDSX * 2)      // 20480 B per tile (A or B)
#define STAGE_BYTES (2 * TILE_BYTES)    // 40960: A, B
#define NSTAGE 4
#define SMEM_TOTAL (NSTAGE * STAGE_BYTES)   // 163840 B, occ 1

#define A_OFF  0
#define B_OFF  TILE_BYTES

// fp16 scratch (device globals: allocation-free per harness rules)
__device__ __half g_xh[(size_t)MDIM * KDIM];
__device__ __half g_wh[(size_t)NDIM * KDIM];

__global__ void split_x_kernel(const float4* __restrict__ x, int n4) {
    int i = blockIdx.x * blockDim.x + threadIdx.x;
    if (i >= n4) return;
    float4 v = x[i];
    __half2* ph = reinterpret_cast<__half2*>(g_xh);
    __half2 a, b;
    a.x = __float2half_rn(v.x); a.y = __float2half_rn(v.y);
    b.x = __float2half_rn(v.z); b.y = __float2half_rn(v.w);
    ph[2 * i] = a; ph[2 * i + 1] = b;
}

__global__ void split_w_kernel(const float4* __restrict__ w,
                               const float4* __restrict__ m, int n4) {
    int i = blockIdx.x * blockDim.x + threadIdx.x;
    if (i >= n4) return;
    float4 wv = w[i];
    float4 mv = m[i];
    __half2* ph = reinterpret_cast<__half2*>(g_wh);
    __half2 a, b;
    a.x = __float2half_rn(wv.x * mv.x); a.y = __float2half_rn(wv.y * mv.y);
    b.x = __float2half_rn(wv.z * mv.z); b.y = __float2half_rn(wv.w * mv.w);
    ph[2 * i] = a; ph[2 * i + 1] = b;
}

#define CP_ASYNC16(dst_u32, src_ptr) \
    asm volatile("cp.async.cg.shared.global [%0], [%1], 16;\n" :: "r"(dst_u32), "l"(src_ptr))
#define CP_COMMIT() asm volatile("cp.async.commit_group;\n" ::: "memory")
#define CP_WAIT2()  asm volatile("cp.async.wait_group 2;\n" ::: "memory")

#define LDSM_X4(r0, r1, r2, r3, addr) \
    asm volatile("ldmatrix.sync.aligned.m8n8.x4.shared.b16 {%0,%1,%2,%3}, [%4];" \
                 : "=r"(r0), "=r"(r1), "=r"(r2), "=r"(r3) : "r"(addr))

#define MMA16816(d, a, b0, b1) \
    asm volatile("mma.sync.aligned.m16n8k16.row.col.f32.f16.f16.f32 " \
                 "{%0,%1,%2,%3}, {%4,%5,%6,%7}, {%8,%9}, {%0,%1,%2,%3};" \
                 : "+f"(d[0]), "+f"(d[1]), "+f"(d[2]), "+f"(d[3]) \
                 : "r"(a[0]), "r"(a[1]), "r"(a[2]), "r"(a[3]), "r"(b0), "r"(b1))

__global__ __launch_bounds__(512, 1)
void gemm_fp16_kernel(float* __restrict__ out, const float* __restrict__ bias) {
    extern __shared__ __align__(16) unsigned char smem_raw[];
    const uint32_t smem_base = (uint32_t)__cvta_generic_to_shared(smem_raw);

    const int tid = threadIdx.x;
    const int lane = tid & 31;
    const int warp = tid >> 5;          // 0..15
    const int wm0 = (warp >> 2) * 64;   // 4 warp rows * 64
    const int wn0 = (warp & 3) * 64;    // 4 warp cols * 64
    const int gm0 = blockIdx.y * BM;
    const int gn0 = blockIdx.x * BN;

    float acc[4][8][4];
    #pragma unroll
    for (int i = 0; i < 4; i++)
        #pragma unroll
        for (int j = 0; j < 8; j++)
            #pragma unroll
            for (int r = 0; r < 4; r++)
                acc[i][j][r] = 0.0f;

    // ---- smem fill: 2x256 rows x 32 cols fp16; 512 thr x 4 chunks of 16B ----
    const int fr = tid >> 2;            // 0..127, two passes of 128 rows
    const int fc = (tid & 3) * 8;       // element offset of 16B chunk

    auto load_stage = [&](int kt, int s) {
        const int k0 = kt * BK;
        const uint32_t sbase = smem_base + (uint32_t)s * STAGE_BYTES;
        #pragma unroll
        for (int p = 0; p < 2; p++) {
            const int row = fr + p * 128;
            const uint32_t d = sbase + (uint32_t)(row * LDSX + fc) * 2;
            const size_t aoff = (size_t)(gm0 + row) * KDIM + k0 + fc;
            const size_t boff = (size_t)(gn0 + row) * KDIM + k0 + fc;
            CP_ASYNC16(d + A_OFF, g_xh + aoff);
            CP_ASYNC16(d + B_OFF, g_wh + boff);
        }
        CP_COMMIT();
    };

    // ldmatrix addressing (rows within tile, col selectors per lane group)
    const int a_row = wm0 + (lane & 15);
    const int a_csel = ((lane >> 4) << 3);
    const int b_row = wn0 + (lane & 7) + ((lane >> 4) << 3);
    const int b_csel = (((lane >> 3) & 1) << 3);

    load_stage(0, 0);
    load_stage(1, 1);
    load_stage(2, 2);

    const int KT = KDIM / BK;   // 64
    for (int kt = 0; kt < KT; kt++) {
        CP_WAIT2();             // 3 groups in flight -> stage kt complete
        __syncthreads();
        if (kt + 3 < KT) load_stage(kt + 3, (kt + 3) & 3);
        else             CP_COMMIT();           // keep group count in lockstep

        const uint32_t sb = smem_base + (uint32_t)(kt & 3) * STAGE_BYTES;

        #pragma unroll
        for (int kk = 0; kk < 2; kk++) {
            const int k0 = kk * 16;
            uint32_t af[4][4];
            #pragma unroll
            for (int im = 0; im < 4; im++) {
                const uint32_t addr =
                    sb + A_OFF + (uint32_t)(((a_row + im * 16) * LDSX) + k0 + a_csel) * 2;
                LDSM_X4(af[im][0], af[im][1], af[im][2], af[im][3], addr);
            }
            uint32_t bh[4][4];
            #pragma unroll
            for (int ib = 0; ib < 4; ib++) {
                const uint32_t addr =
                    sb + B_OFF + (uint32_t)(((b_row + ib * 16) * LDSX) + k0 + b_csel) * 2;
                LDSM_X4(bh[ib][0], bh[ib][1], bh[ib][2], bh[ib][3], addr);
            }
            #pragma unroll
            for (int im = 0; im < 4; im++) {
                #pragma unroll
                for (int in = 0; in < 8; in++) {
                    const int g = in >> 1;
                    const int o = (in & 1) * 2;
                    MMA16816(acc[im][in], af[im], bh[g][o], bh[g][o + 1]);
                }
            }
        }
    }

    // ---- epilogue ----
    #pragma unroll
    for (int im = 0; im < 4; im++) {
        #pragma unroll
        for (int in = 0; in < 8; in++) {
            const int row = gm0 + wm0 + im * 16 + (lane >> 2);
            const int col = gn0 + wn0 + in * 8 + ((lane & 3) << 1);
            const float b0 = bias[col];
            const float b1 = bias[col + 1];
            float2 v0 = make_float2(acc[im][in][0] + b0, acc[im][in][1] + b1);
            float2 v1 = make_float2(acc[im][in][2] + b0, acc[im][in][3] + b1);
            *reinterpret_cast<float2*>(out + (size_t)row * NDIM + col) = v0;
            *reinterpret_cast<float2*>(out + (size_t)(row + 8) * NDIM + col) = v1;
        }
    }
}

extern "C" void kernel_launch(void* const* d_in, const int* in_sizes, int n_in,
                              void* d_out, int out_size) {
    const float* x    = (const float*)d_in[0];
    const float* w    = (const float*)d_in[1];
    const float* bias = (const float*)d_in[2];
    const float* mask = (const float*)d_in[3];

    const int nx4 = (MDIM * KDIM) / 4;   // 8388608
    const int nw4 = (NDIM * KDIM) / 4;   // 1048576
    split_x_kernel<<<(nx4 + 255) / 256, 256>>>((const float4*)x, nx4);
    split_w_kernel<<<(nw4 + 255) / 256, 256>>>((const float4*)w, (const float4*)mask, nw4);

    cudaFuncSetAttribute(gemm_fp16_kernel,
                         cudaFuncAttributeMaxDynamicSharedMemorySize, SMEM_TOTAL);
    dim3 grid(NDIM / BN, MDIM / BM);   // (8, 64)
    gemm_fp16_kernel<<<grid, 512, SMEM_TOTAL>>>((float*)d_out, bias);
}

// round 14
// speedup vs baseline: 1.5130x; 1.5130x over previous
#include <cuda_runtime.h>
#include <cuda_fp16.h>
#include <cstdint>

#define MDIM 16384
#define NDIM 2048
#define KDIM 2048

#define BM 256
#define BN 128
#define BK 32
#define LDSX 40                         // padded smem row stride (elements)
#define A_BYTES (BM * LDSX * 2)         // 20480
#define B_BYTES (BN * LDSX * 2)         // 10240
#define STAGE_BYTES (A_BYTES + B_BYTES) // 30720
#define NSTAGE 4
#define SMEM_TOTAL (NSTAGE * STAGE_BYTES)   // 122880 B

#define A_OFF  0
#define B_OFF  A_BYTES

// fp16 scratch (device globals: allocation-free per harness rules)
__device__ __half g_xh[(size_t)MDIM * KDIM];
__device__ __half g_wh[(size_t)NDIM * KDIM];

__global__ void split_x_kernel(const float4* __restrict__ x, int n4) {
    int i = blockIdx.x * blockDim.x + threadIdx.x;
    if (i >= n4) return;
    float4 v = x[i];
    __half2* ph = reinterpret_cast<__half2*>(g_xh);
    __half2 a, b;
    a.x = __float2half_rn(v.x); a.y = __float2half_rn(v.y);
    b.x = __float2half_rn(v.z); b.y = __float2half_rn(v.w);
    ph[2 * i] = a; ph[2 * i + 1] = b;
}

__global__ void split_w_kernel(const float4* __restrict__ w,
                               const float4* __restrict__ m, int n4) {
    int i = blockIdx.x * blockDim.x + threadIdx.x;
    if (i >= n4) return;
    float4 wv = w[i];
    float4 mv = m[i];
    __half2* ph = reinterpret_cast<__half2*>(g_wh);
    __half2 a, b;
    a.x = __float2half_rn(wv.x * mv.x); a.y = __float2half_rn(wv.y * mv.y);
    b.x = __float2half_rn(wv.z * mv.z); b.y = __float2half_rn(wv.w * mv.w);
    ph[2 * i] = a; ph[2 * i + 1] = b;
}

#define CP_ASYNC16(dst_u32, src_ptr) \
    asm volatile("cp.async.cg.shared.global [%0], [%1], 16;\n" :: "r"(dst_u32), "l"(src_ptr))
#define CP_COMMIT() asm volatile("cp.async.commit_group;\n" ::: "memory")
#define CP_WAIT2()  asm volatile("cp.async.wait_group 2;\n" ::: "memory")

#define LDSM_X4(r0, r1, r2, r3, addr) \
    asm volatile("ldmatrix.sync.aligned.m8n8.x4.shared.b16 {%0,%1,%2,%3}, [%4];" \
                 : "=r"(r0), "=r"(r1), "=r"(r2), "=r"(r3) : "r"(addr))

#define MMA16816(d, a, b0, b1) \
    asm volatile("mma.sync.aligned.m16n8k16.row.col.f32.f16.f16.f32 " \
                 "{%0,%1,%2,%3}, {%4,%5,%6,%7}, {%8,%9}, {%0,%1,%2,%3};" \
                 : "+f"(d[0]), "+f"(d[1]), "+f"(d[2]), "+f"(d[3]) \
                 : "r"(a[0]), "r"(a[1]), "r"(a[2]), "r"(a[3]), "r"(b0), "r"(b1))

__global__ __launch_bounds__(512, 1)
void gemm_fp16_kernel(float* __restrict__ out, const float* __restrict__ bias) {
    extern __shared__ __align__(16) unsigned char smem_raw[];
    const uint32_t smem_base = (uint32_t)__cvta_generic_to_shared(smem_raw);

    const int tid = threadIdx.x;
    const int lane = tid & 31;
    const int warp = tid >> 5;          // 0..15
    const int wm0 = (warp >> 2) * 64;   // 4 warp rows * 64 = 256
    const int wn0 = (warp & 3) * 32;    // 4 warp cols * 32 = 128
    const int gm0 = blockIdx.y * BM;
    const int gn0 = blockIdx.x * BN;

    float acc[4][4][4];
    #pragma unroll
    for (int i = 0; i < 4; i++)
        #pragma unroll
        for (int j = 0; j < 4; j++)
            #pragma unroll
            for (int r = 0; r < 4; r++)
                acc[i][j][r] = 0.0f;

    // ---- smem fill: 384 rows (256 A + 128 B) x 32 cols; 1536 16B-chunks ----
    auto load_stage = [&](int kt, int s) {
        const int k0 = kt * BK;
        const uint32_t sbase = smem_base + (uint32_t)s * STAGE_BYTES;
        #pragma unroll
        for (int j = 0; j < 3; j++) {
            const int c = tid + j * 512;          // 0..1535
            const int row = c >> 2;               // 0..383
            const int ci = (c & 3) * 8;           // element offset of 16B chunk
            if (row < BM) {
                const uint32_t d = sbase + A_OFF + (uint32_t)(row * LDSX + ci) * 2;
                CP_ASYNC16(d, g_xh + (size_t)(gm0 + row) * KDIM + k0 + ci);
            } else {
                const int br = row - BM;
                const uint32_t d = sbase + B_OFF + (uint32_t)(br * LDSX + ci) * 2;
                CP_ASYNC16(d, g_wh + (size_t)(gn0 + br) * KDIM + k0 + ci);
            }
        }
        CP_COMMIT();
    };

    // ldmatrix addressing (rows within tile, col selectors per lane group)
    const int a_row = wm0 + (lane & 15);
    const int a_csel = ((lane >> 4) << 3);
    const int b_row = wn0 + (lane & 7) + ((lane >> 4) << 3);
    const int b_csel = (((lane >> 3) & 1) << 3);

    load_stage(0, 0);
    load_stage(1, 1);
    load_stage(2, 2);

    const int KT = KDIM / BK;   // 64
    for (int kt = 0; kt < KT; kt++) {
        CP_WAIT2();             // 3 groups in flight -> stage kt complete
        __syncthreads();
        if (kt + 3 < KT) load_stage(kt + 3, (kt + 3) & 3);
        else             CP_COMMIT();           // keep group count in lockstep

        const uint32_t sb = smem_base + (uint32_t)(kt & 3) * STAGE_BYTES;

        #pragma unroll
        for (int kk = 0; kk < 2; kk++) {
            const int k0 = kk * 16;
            uint32_t af[4][4];
            #pragma unroll
            for (int im = 0; im < 4; im++) {
                const uint32_t addr =
                    sb + A_OFF + (uint32_t)(((a_row + im * 16) * LDSX) + k0 + a_csel) * 2;
                LDSM_X4(af[im][0], af[im][1], af[im][2], af[im][3], addr);
            }
            uint32_t bh[2][4];
            #pragma unroll
            for (int ib = 0; ib < 2; ib++) {
                const uint32_t addr =
                    sb + B_OFF + (uint32_t)(((b_row + ib * 16) * LDSX) + k0 + b_csel) * 2;
                LDSM_X4(bh[ib][0], bh[ib][1], bh[ib][2], bh[ib][3], addr);
            }
            #pragma unroll
            for (int im = 0; im < 4; im++) {
                #pragma unroll
                for (int in = 0; in < 4; in++) {
                    const int g = in >> 1;
                    const int o = (in & 1) * 2;
                    MMA16816(acc[im][in], af[im], bh[g][o], bh[g][o + 1]);
                }
            }
        }
    }

    // ---- epilogue ----
    #pragma unroll
    for (int im = 0; im < 4; im++) {
        #pragma unroll
        for (int in = 0; in < 4; in++) {
            const int row = gm0 + wm0 + im * 16 + (lane >> 2);
            const int col = gn0 + wn0 + in * 8 + ((lane & 3) << 1);
            const float b0 = bias[col];
            const float b1 = bias[col + 1];
            float2 v0 = make_float2(acc[im][in][0] + b0, acc[im][in][1] + b1);
            float2 v1 = make_float2(acc[im][in][2] + b0, acc[im][in][3] + b1);
            *reinterpret_cast<float2*>(out + (size_t)row * NDIM + col) = v0;
            *reinterpret_cast<float2*>(out + (size_t)(row + 8) * NDIM + col) = v1;
        }
    }
}

extern "C" void kernel_launch(void* const* d_in, const int* in_sizes, int n_in,
                              void* d_out, int out_size) {
    const float* x    = (const float*)d_in[0];
    const float* w    = (const float*)d_in[1];
    const float* bias = (const float*)d_in[2];
    const float* mask = (const float*)d_in[3];

    const int nx4 = (MDIM * KDIM) / 4;   // 8388608
    const int nw4 = (NDIM * KDIM) / 4;   // 1048576
    split_x_kernel<<<(nx4 + 255) / 256, 256>>>((const float4*)x, nx4);
    split_w_kernel<<<(nw4 + 255) / 256, 256>>>((const float4*)w, (const float4*)mask, nw4);

    cudaFuncSetAttribute(gemm_fp16_kernel,
                         cudaFuncAttributeMaxDynamicSharedMemorySize, SMEM_TOTAL);
    dim3 grid(NDIM / BN, MDIM / BM);   // (16, 64)
    gemm_fp16_kernel<<<grid, 512, SMEM_TOTAL>>>((float*)d_out, bias);
}

// round 15
// speedup vs baseline: 2.7486x; 1.8166x over previous
#include <cuda_runtime.h>
#include <cuda_fp16.h>
#include <cstdint>

#define MDIM 16384
#define NDIM 2048
#define KDIM 2048

#define BM 128
#define BN 128
#define BK 64
#define LDSX 72                         // padded smem row stride (elements), 144B rows
#define TILE_BYTES (BM * LDSX * 2)      // 18432 B per tile
#define STAGE_BYTES (2 * TILE_BYTES)    // 36864: A, B
#define NSTAGE 3
#define SMEM_TOTAL (NSTAGE * STAGE_BYTES)   // 110592 B -> 2 CTAs/SM (216KB)

#define A_OFF  0
#define B_OFF  TILE_BYTES

// fp16 scratch (device globals: allocation-free per harness rules)
__device__ __half g_xh[(size_t)MDIM * KDIM];
__device__ __half g_wh[(size_t)NDIM * KDIM];

__global__ void split_x_kernel(const float4* __restrict__ x, int n4) {
    int i = blockIdx.x * blockDim.x + threadIdx.x;
    if (i >= n4) return;
    float4 v = x[i];
    __half2* ph = reinterpret_cast<__half2*>(g_xh);
    __half2 a, b;
    a.x = __float2half_rn(v.x); a.y = __float2half_rn(v.y);
    b.x = __float2half_rn(v.z); b.y = __float2half_rn(v.w);
    ph[2 * i] = a; ph[2 * i + 1] = b;
}

__global__ void split_w_kernel(const float4* __restrict__ w,
                               const float4* __restrict__ m, int n4) {
    int i = blockIdx.x * blockDim.x + threadIdx.x;
    if (i >= n4) return;
    float4 wv = w[i];
    float4 mv = m[i];
    __half2* ph = reinterpret_cast<__half2*>(g_wh);
    __half2 a, b;
    a.x = __float2half_rn(wv.x * mv.x); a.y = __float2half_rn(wv.y * mv.y);
    b.x = __float2half_rn(wv.z * mv.z); b.y = __float2half_rn(wv.w * mv.w);
    ph[2 * i] = a; ph[2 * i + 1] = b;
}

#define CP_ASYNC16(dst_u32, src_ptr) \
    asm volatile("cp.async.cg.shared.global [%0], [%1], 16;\n" :: "r"(dst_u32), "l"(src_ptr))
#define CP_COMMIT() asm volatile("cp.async.commit_group;\n" ::: "memory")
#define CP_WAIT1()  asm volatile("cp.async.wait_group 1;\n" ::: "memory")

#define LDSM_X4(r0, r1, r2, r3, addr) \
    asm volatile("ldmatrix.sync.aligned.m8n8.x4.shared.b16 {%0,%1,%2,%3}, [%4];" \
                 : "=r"(r0), "=r"(r1), "=r"(r2), "=r"(r3) : "r"(addr))

#define MMA16816(d, a, b0, b1) \
    asm volatile("mma.sync.aligned.m16n8k16.row.col.f32.f16.f16.f32 " \
                 "{%0,%1,%2,%3}, {%4,%5,%6,%7}, {%8,%9}, {%0,%1,%2,%3};" \
                 : "+f"(d[0]), "+f"(d[1]), "+f"(d[2]), "+f"(d[3]) \
                 : "r"(a[0]), "r"(a[1]), "r"(a[2]), "r"(a[3]), "r"(b0), "r"(b1))

__global__ __launch_bounds__(256, 2)
void gemm_fp16_kernel(float* __restrict__ out, const float* __restrict__ bias) {
    extern __shared__ __align__(16) unsigned char smem_raw[];
    const uint32_t smem_base = (uint32_t)__cvta_generic_to_shared(smem_raw);

    const int tid = threadIdx.x;
    const int lane = tid & 31;
    const int warp = tid >> 5;
    const int wm0 = (warp >> 2) * 64;   // 2 warp rows * 64
    const int wn0 = (warp & 3) * 32;    // 4 warp cols * 32
    const int gm0 = blockIdx.y * BM;
    const int gn0 = blockIdx.x * BN;

    float acc[4][4][4];
    #pragma unroll
    for (int i = 0; i < 4; i++)
        #pragma unroll
        for (int j = 0; j < 4; j++)
            #pragma unroll
            for (int r = 0; r < 4; r++)
                acc[i][j][r] = 0.0f;

    // ---- smem fill: 2 tiles x 128 rows x 64 cols fp16; 2048 16B-chunks ----
    auto load_stage = [&](int kt, int s) {
        const int k0 = kt * BK;
        const uint32_t sbase = smem_base + (uint32_t)s * STAGE_BYTES;
        #pragma unroll
        for (int j = 0; j < 4; j++) {
            const int c = tid + j * 256;          // 0..1023
            const int row = c >> 3;               // 0..127
            const int ci = (c & 7) * 8;           // element offset of 16B chunk
            const uint32_t d = sbase + (uint32_t)(row * LDSX + ci) * 2;
            CP_ASYNC16(d + A_OFF, g_xh + (size_t)(gm0 + row) * KDIM + k0 + ci);
            CP_ASYNC16(d + B_OFF, g_wh + (size_t)(gn0 + row) * KDIM + k0 + ci);
        }
        CP_COMMIT();
    };

    // ldmatrix addressing (rows within tile, col selectors per lane group)
    const int a_row = wm0 + (lane & 15);
    const int a_csel = ((lane >> 4) << 3);
    const int b_row = wn0 + (lane & 7) + ((lane >> 4) << 3);
    const int b_csel = (((lane >> 3) & 1) << 3);

    load_stage(0, 0);
    load_stage(1, 1);

    const int KT = KDIM / BK;   // 32
    for (int kt = 0; kt < KT; kt++) {
        CP_WAIT1();             // stage kt complete (kt+1 still in flight)
        __syncthreads();
        if (kt + 2 < KT) load_stage(kt + 2, (kt + 2) % NSTAGE);
        else             CP_COMMIT();           // keep group count in lockstep

        const uint32_t sb = smem_base + (uint32_t)(kt % NSTAGE) * STAGE_BYTES;

        #pragma unroll
        for (int kk = 0; kk < 4; kk++) {
            const int k0 = kk * 16;
            uint32_t af[4][4];
            #pragma unroll
            for (int im = 0; im < 4; im++) {
                const uint32_t addr =
                    sb + A_OFF + (uint32_t)(((a_row + im * 16) * LDSX) + k0 + a_csel) * 2;
                LDSM_X4(af[im][0], af[im][1], af[im][2], af[im][3], addr);
            }
            uint32_t bh[2][4];
            #pragma unroll
            for (int ib = 0; ib < 2; ib++) {
                const uint32_t addr =
                    sb + B_OFF + (uint32_t)(((b_row + ib * 16) * LDSX) + k0 + b_csel) * 2;
                LDSM_X4(bh[ib][0], bh[ib][1], bh[ib][2], bh[ib][3], addr);
            }
            #pragma unroll
            for (int im = 0; im < 4; im++) {
                #pragma unroll
                for (int in = 0; in < 4; in++) {
                    const int g = in >> 1;
                    const int o = (in & 1) * 2;
                    MMA16816(acc[im][in], af[im], bh[g][o], bh[g][o + 1]);
                }
            }
        }
    }

    // ---- epilogue ----
    #pragma unroll
    for (int im = 0; im < 4; im++) {
        #pragma unroll
        for (int in = 0; in < 4; in++) {
            const int row = gm0 + wm0 + im * 16 + (lane >> 2);
            const int col = gn0 + wn0 + in * 8 + ((lane & 3) << 1);
            const float b0 = bias[col];
            const float b1 = bias[col + 1];
            float2 v0 = make_float2(acc[im][in][0] + b0, acc[im][in][1] + b1);
            float2 v1 = make_float2(acc[im][in][2] + b0, acc[im][in][3] + b1);
            *reinterpret_cast<float2*>(out + (size_t)row * NDIM + col) = v0;
            *reinterpret_cast<float2*>(out + (size_t)(row + 8) * NDIM + col) = v1;
        }
    }
}

extern "C" void kernel_launch(void* const* d_in, const int* in_sizes, int n_in,
                              void* d_out, int out_size) {
    const float* x    = (const float*)d_in[0];
    const float* w    = (const float*)d_in[1];
    const float* bias = (const float*)d_in[2];
    const float* mask = (const float*)d_in[3];

    const int nx4 = (MDIM * KDIM) / 4;   // 8388608
    const int nw4 = (NDIM * KDIM) / 4;   // 1048576
    split_x_kernel<<<(nx4 + 255) / 256, 256>>>((const float4*)x, nx4);
    split_w_kernel<<<(nw4 + 255) / 256, 256>>>((const float4*)w, (const float4*)mask, nw4);

    cudaFuncSetAttribute(gemm_fp16_kernel,
                         cudaFuncAttributeMaxDynamicSharedMemorySize, SMEM_TOTAL);
    dim3 grid(NDIM / BN, MDIM / BM);   // (16, 128)
    gemm_fp16_kernel<<<grid, 256, SMEM_TOTAL>>>((float*)d_out, bias);
}